// round 12
// baseline (speedup 1.0000x reference)
#include <cuda_runtime.h>

#define P    128
#define NT   256
#define PT   132   // pitch for sT / sD (skewed)
#define PLT  132   // pitch for LshT (multiple of 4 -> aligned float4 rows)

typedef unsigned long long u64;

struct __align__(16) Smem {
  float sT[P][PT];      // Theta (orig), later Theta+Delta (symmetric)
  float sD[P][PT];      // Tc buffer, later Delta (symmetric, zero diag)
  float LshT[127][PLT]; // LshT[m][j] = L_w[j][m]; column j=127 zeroed
  float rowA[2][PT];    // sweep: pivot row k   (with [k]   -= 1), dbl-buffered
  float rowB[2][PT];    // sweep: pivot row k+1 (with [k+1] -= 1), dbl-buffered
  float tvec[2][PT];    // scan: t-hat (double-buffered, gapped)
  float dvec[2][PT];    // scan: d-hat (double-buffered, gapped)
  float gsh[2][PT];     // scan: W row c (double-buffered, gapped)
  float uvec[2][PT];    // scan: u = W t-hat (double-buffered, uvec[c]=u[c]-1)
  float redT[2][8];
  float redD[2][8];
  float ucvc[2][2];
  float diag[P];
};

// gapped index: halves offset by +4 floats -> warp halves hit different banks
__device__ __forceinline__ int VIDX(int x) { return x + ((x >> 6) << 2); }

__device__ __forceinline__ u64 pk2s(float x) {
  u64 r; asm("mov.b64 %0,{%1,%1};" : "=l"(r) : "f"(x)); return r;
}
__device__ __forceinline__ u64 pk2(float x, float y) {
  u64 r; asm("mov.b64 %0,{%1,%2};" : "=l"(r) : "f"(x), "f"(y)); return r;
}
__device__ __forceinline__ float2 up2(u64 a) {
  float2 f; asm("mov.b64 {%0,%1},%2;" : "=f"(f.x), "=f"(f.y) : "l"(a)); return f;
}
__device__ __forceinline__ u64 f2ma(u64 a, u64 b, u64 c) {
  u64 d; asm("fma.rn.f32x2 %0,%1,%2,%3;" : "=l"(d) : "l"(a), "l"(b), "l"(c));
  return d;
}
__device__ __forceinline__ float frcp(float x) {
  float r; asm("rcp.approx.f32 %0,%1;" : "=f"(r) : "f"(x)); return r;
}

__global__ void __launch_bounds__(NT, 1)
spod_kernel(const float* __restrict__ Theta,
            const float* __restrict__ Lw,
            float* __restrict__ Out)
{
  extern __shared__ __align__(16) float smraw[];
  Smem* sm = reinterpret_cast<Smem*>(smraw);

  const int tid = threadIdx.x;
  const int b   = blockIdx.x;
  const int i   = tid >> 1;      // row owned by this thread
  const int jh  = tid & 1;       // which 64-column half
  const int j0  = jh << 6;       // 0 or 64
  const int vb  = jh ? 68 : 0;   // VIDX(j0)

  const float* Tin = Theta + (size_t)b * (P * P);

  // ---------------- Phase A: load Theta, L_w (transposed) ----------------
  for (int idx = tid; idx < P * P; idx += NT)
    sm->sT[idx >> 7][idx & 127] = Tin[idx];
  for (int idx = tid; idx < 127 * 127; idx += NT) {
    int m = idx / 127, j = idx - m * 127;     // conflict-free STS rows
    sm->LshT[m][j] = Lw[j * 127 + m];
  }
  if (tid < 127) sm->LshT[tid][127] = 0.0f;
  if (tid < PT) { sm->uvec[1][tid] = 0.0f; sm->gsh[1][tid] = 0.0f; }
  __syncthreads();

  // ---------------- Phase B0: Tc[m][c] = Theta[m + (m>=c)][c] ----------------
  for (int idx = tid; idx < 127 * P; idx += NT) {
    int m = idx >> 7, c = idx & 127;
    sm->sD[m][c] = sm->sT[m + (m >= c)][c];
  }
  __syncthreads();

  // ---------------- Phase B1: Y = L_w @ Tc (packed f32x2) ----------------
  const int tj = tid >> 4, ti = tid & 15;
  const int jr = tj * 8, ic = ti * 8;
  u64 acc2[8][4];
  #pragma unroll
  for (int r = 0; r < 8; ++r)
    #pragma unroll
    for (int s = 0; s < 4; ++s) acc2[r][s] = 0ULL;

  #pragma unroll 1
  for (int m = 0; m < 127; ++m) {
    ulonglong2 ta = *(const ulonglong2*)&sm->sD[m][ic];
    ulonglong2 tb = *(const ulonglong2*)&sm->sD[m][ic + 4];
    float4 lv0 = *(const float4*)&sm->LshT[m][jr];
    float4 lv1 = *(const float4*)&sm->LshT[m][jr + 4];
    u64 l0 = pk2s(lv0.x), l1 = pk2s(lv0.y), l2 = pk2s(lv0.z), l3 = pk2s(lv0.w);
    u64 l4 = pk2s(lv1.x), l5 = pk2s(lv1.y), l6 = pk2s(lv1.z), l7 = pk2s(lv1.w);
    acc2[0][0] = f2ma(l0, ta.x, acc2[0][0]);
    acc2[0][1] = f2ma(l0, ta.y, acc2[0][1]);
    acc2[0][2] = f2ma(l0, tb.x, acc2[0][2]);
    acc2[0][3] = f2ma(l0, tb.y, acc2[0][3]);
    acc2[1][0] = f2ma(l1, ta.x, acc2[1][0]);
    acc2[1][1] = f2ma(l1, ta.y, acc2[1][1]);
    acc2[1][2] = f2ma(l1, tb.x, acc2[1][2]);
    acc2[1][3] = f2ma(l1, tb.y, acc2[1][3]);
    acc2[2][0] = f2ma(l2, ta.x, acc2[2][0]);
    acc2[2][1] = f2ma(l2, ta.y, acc2[2][1]);
    acc2[2][2] = f2ma(l2, tb.x, acc2[2][2]);
    acc2[2][3] = f2ma(l2, tb.y, acc2[2][3]);
    acc2[3][0] = f2ma(l3, ta.x, acc2[3][0]);
    acc2[3][1] = f2ma(l3, ta.y, acc2[3][1]);
    acc2[3][2] = f2ma(l3, tb.x, acc2[3][2]);
    acc2[3][3] = f2ma(l3, tb.y, acc2[3][3]);
    acc2[4][0] = f2ma(l4, ta.x, acc2[4][0]);
    acc2[4][1] = f2ma(l4, ta.y, acc2[4][1]);
    acc2[4][2] = f2ma(l4, tb.x, acc2[4][2]);
    acc2[4][3] = f2ma(l4, tb.y, acc2[4][3]);
    acc2[5][0] = f2ma(l5, ta.x, acc2[5][0]);
    acc2[5][1] = f2ma(l5, ta.y, acc2[5][1]);
    acc2[5][2] = f2ma(l5, tb.x, acc2[5][2]);
    acc2[5][3] = f2ma(l5, tb.y, acc2[5][3]);
    acc2[6][0] = f2ma(l6, ta.x, acc2[6][0]);
    acc2[6][1] = f2ma(l6, ta.y, acc2[6][1]);
    acc2[6][2] = f2ma(l6, tb.x, acc2[6][2]);
    acc2[6][3] = f2ma(l6, tb.y, acc2[6][3]);
    acc2[7][0] = f2ma(l7, ta.x, acc2[7][0]);
    acc2[7][1] = f2ma(l7, ta.y, acc2[7][1]);
    acc2[7][2] = f2ma(l7, tb.x, acc2[7][2]);
    acc2[7][3] = f2ma(l7, tb.y, acc2[7][3]);
  }
  __syncthreads();

  // ---------------- Phase B2: Delta (symmetric) into sD ----------------
  #pragma unroll
  for (int r = 0; r < 8; ++r) {
    int j = jr + r;
    #pragma unroll
    for (int s = 0; s < 4; ++s) {
      float2 f = up2(acc2[r][s]);
      int i0 = ic + 2 * s, i1 = i0 + 1;
      if (j < i0) { float d0 = f.x - sm->sT[j][i0]; sm->sD[i0][j] = d0; sm->sD[j][i0] = d0; }
      if (j < i1) { float d1 = f.y - sm->sT[j][i1]; sm->sD[i1][j] = d1; sm->sD[j][i1] = d1; }
    }
  }
  if (tid < P) sm->sD[tid][tid] = 0.0f;
  __syncthreads();

  // ---------------- Phase C: W = inv(Theta), 2-pivot blocked sweep ----------------
  u64 W2[32];
  #pragma unroll
  for (int t = 0; t < 16; ++t) {
    ulonglong2 v = *(const ulonglong2*)&sm->sT[i][j0 + 4 * t];
    W2[2 * t] = v.x; W2[2 * t + 1] = v.y;
  }

  #pragma unroll 1
  for (int k = 0; k < P; k += 2) {
    const int buf = (k >> 1) & 1;
    if (i == k || i == k + 1) {
      float* dst = (i == k) ? sm->rowA[buf] : sm->rowB[buf];
      #pragma unroll
      for (int t = 0; t < 16; ++t) {
        ulonglong2 o; o.x = W2[2 * t]; o.y = W2[2 * t + 1];
        *(ulonglong2*)&dst[vb + 4 * t] = o;
      }
      if ((i >> 6) == jh)            // my half holds column i: [i] -= 1 fixup
        dst[VIDX(i)] -= 1.0f;
    }
    __syncthreads();

    float a_k  = sm->rowA[buf][VIDX(k)];      // d00 - 1
    float a_k1 = sm->rowA[buf][VIDX(k + 1)];  // d01
    float b_k1 = sm->rowB[buf][VIDX(k + 1)];  // d11 - 1
    float d00 = a_k + 1.0f, d01 = a_k1, d11 = b_k1 + 1.0f;
    float rdet = frcp(d00 * d11 - d01 * d01);
    float i00 = d11 * rdet, i01 = -d01 * rdet, i11 = d00 * rdet;
    float c1 = sm->rowA[buf][VIDX(i)];
    float c2 = sm->rowB[buf][VIDX(i)];
    float g1 = c1 * i00 + c2 * i01;
    float g2 = c1 * i01 + c2 * i11;
    u64 ng1 = pk2s(-g1), ng2 = pk2s(-g2);
    #pragma unroll
    for (int t = 0; t < 16; ++t) {
      ulonglong2 rA = *(const ulonglong2*)&sm->rowA[buf][vb + 4 * t];
      ulonglong2 rB = *(const ulonglong2*)&sm->rowB[buf][vb + 4 * t];
      W2[2 * t]     = f2ma(ng2, rB.x, f2ma(ng1, rA.x, W2[2 * t]));
      W2[2 * t + 1] = f2ma(ng2, rB.y, f2ma(ng1, rA.y, W2[2 * t + 1]));
    }
  }

  // negate (sweep gives -A^{-1}), then fix the constant +2 pivot-diag error
  #pragma unroll
  for (int t = 0; t < 32; ++t) W2[t] ^= 0x8000000080000000ULL;
  if ((i >> 6) == jh) {
    int p = i - j0;
    #pragma unroll
    for (int t = 0; t < 32; ++t)
      if (t == (p >> 1)) {
        float2 f = up2(W2[t]);
        if (p & 1) f.y += 2.0f; else f.x += 2.0f;
        W2[t] = pk2(f.x, f.y);
      }
  }

  // ---------------- Phase D: Theta += Delta ----------------
  #pragma unroll
  for (int t = 0; t < 16; ++t) {
    float4 a4 = *(const float4*)&sm->sT[i][j0 + 4 * t];
    float4 d4 = *(const float4*)&sm->sD[i][j0 + 4 * t];
    a4.x += d4.x; a4.y += d4.y; a4.z += d4.z; a4.w += d4.w;
    *(float4*)&sm->sT[i][j0 + 4 * t] = a4;
  }
  __syncthreads();

  // ---------------- Phase E prologue: vectors for c=0 ----------------
  {
    int r5 = tid & 127;
    if (tid < 128) sm->tvec[0][VIDX(r5)] = (r5 == 0) ? 0.0f : sm->sT[0][r5];
    else           sm->dvec[0][VIDX(r5)] = (r5 == 0) ? 0.0f : sm->sD[0][r5];
  }
  __syncthreads();

  // ---------------- Phase E: sequential column scan (1 barrier / step) ----------------
  float e1s = 0.0f, e2s = 0.0f;   // update coefficients from previous step
  #pragma unroll 1
  for (int c = 0; c < P; ++c) {
    const int cb = c & 1;          // current write buffer / tvec read buffer
    const int pb = cb ^ 1;         // previous buffer (gsh/uvec read)
    const int vc = VIDX(c);
    u64 e1p = pk2s(e1s), e2p = pk2s(e2s);

    // prefetch next t-hat / d-hat early (independent; hides under the loop)
    int cn = c + 1;
    if (cn < P) {
      int r5 = tid & 127;
      if (tid < 128) sm->tvec[pb][VIDX(r5)] = (r5 == cn) ? 0.0f : sm->sT[cn][r5];
      else           sm->dvec[pb][VIDX(r5)] = (r5 == cn) ? 0.0f : sm->sD[cn][r5];
    }

    // -- fused: W += e1*g + e2*u (step c-1), then ua += W t-hat, va += W d-hat --
    u64 ua[4] = {0, 0, 0, 0}, va[4] = {0, 0, 0, 0};
    #pragma unroll
    for (int t = 0; t < 16; ++t) {
      ulonglong2 gv = *(const ulonglong2*)&sm->gsh[pb][vb + 4 * t];
      ulonglong2 uv = *(const ulonglong2*)&sm->uvec[pb][vb + 4 * t];
      u64 w0 = f2ma(e2p, uv.x, f2ma(e1p, gv.x, W2[2 * t]));
      u64 w1 = f2ma(e2p, uv.y, f2ma(e1p, gv.y, W2[2 * t + 1]));
      W2[2 * t] = w0; W2[2 * t + 1] = w1;
      ulonglong2 tv = *(const ulonglong2*)&sm->tvec[cb][vb + 4 * t];
      ulonglong2 dv = *(const ulonglong2*)&sm->dvec[cb][vb + 4 * t];
      ua[(2 * t) & 3]     = f2ma(w0, tv.x, ua[(2 * t) & 3]);
      ua[(2 * t + 1) & 3] = f2ma(w1, tv.y, ua[(2 * t + 1) & 3]);
      va[(2 * t) & 3]     = f2ma(w0, dv.x, va[(2 * t) & 3]);
      va[(2 * t + 1) & 3] = f2ma(w1, dv.y, va[(2 * t + 1) & 3]);
    }
    float2 a0 = up2(ua[0]), a1 = up2(ua[1]), a2 = up2(ua[2]), a3 = up2(ua[3]);
    float up = ((a0.x + a0.y) + (a1.x + a1.y)) + ((a2.x + a2.y) + (a3.x + a3.y));
    float2 b0 = up2(va[0]), b1 = up2(va[1]), b2 = up2(va[2]), b3 = up2(va[3]);
    float vp = ((b0.x + b0.y) + (b1.x + b1.y)) + ((b2.x + b2.y) + (b3.x + b3.y));

    float ti_ = sm->tvec[cb][VIDX(i)];
    float di_ = sm->dvec[cb][VIDX(i)];
    float s1p = ti_ * up;
    float scp = di_ * vp;

    // combine halves (partner = tid^1, same warp)
    float uf = up + __shfl_xor_sync(0xffffffffu, up, 1);
    float vf = vp + __shfl_xor_sync(0xffffffffu, vp, 1);
    if (jh == 0) {
      if (i == c) {
        sm->ucvc[cb][0] = uf; sm->ucvc[cb][1] = vf;
        sm->uvec[cb][vc] = uf - 1.0f;     // bakes q[c] = -1 into generic update
      } else {
        sm->uvec[cb][VIDX(i)] = uf;
      }
    }
    if (i == c) {   // W2 is W_c now; publish row c for scalars + next update
      #pragma unroll
      for (int t = 0; t < 16; ++t) {
        ulonglong2 o; o.x = W2[2 * t]; o.y = W2[2 * t + 1];
        *(ulonglong2*)&sm->gsh[cb][vb + 4 * t] = o;
      }
    }

    #pragma unroll
    for (int o = 16; o > 0; o >>= 1) {
      s1p += __shfl_xor_sync(0xffffffffu, s1p, o);
      scp += __shfl_xor_sync(0xffffffffu, scp, o);
    }
    if ((tid & 31) == 0) { sm->redT[cb][tid >> 5] = s1p; sm->redD[cb][tid >> 5] = scp; }
    __syncthreads();

    // -- scalars for step c (parallel-rcp form); applied at start of step c+1 --
    float4 rt0 = *(const float4*)&sm->redT[cb][0];
    float4 rt1 = *(const float4*)&sm->redT[cb][4];
    float4 rd0 = *(const float4*)&sm->redD[cb][0];
    float4 rd1 = *(const float4*)&sm->redD[cb][4];
    float dott = ((rt0.x + rt0.y) + (rt0.z + rt0.w)) + ((rt1.x + rt1.y) + (rt1.z + rt1.w));
    float dotd = ((rd0.x + rd0.y) + (rd0.z + rd0.w)) + ((rd1.x + rd1.y) + (rd1.z + rd1.w));

    float uc   = sm->ucvc[cb][0];
    float vcv  = sm->ucvc[cb][1];
    float w22  = sm->gsh[cb][vc];
    float Tcc  = sm->sT[c][c];
    float iw22 = frcp(w22);
    // w22n = 1/(t22n - s1) = w22 / D,  D = (Tcc + dotd - dott)*w22 + uc^2 - vcv^2
    float D    = fmaf(Tcc + dotd - dott, w22, uc * uc - vcv * vcv);
    float w22n = w22 * frcp(D);                 // two independent rcps
    float alpha = uc * iw22;

    float gi = sm->gsh[cb][VIDX(i)];
    float ui = sm->uvec[cb][VIDX(i)];
    float qi = fmaf(-alpha, gi, ui);
    float cq = w22n * qi;
    e2s = cq;
    e1s = fmaf(-cq, alpha, -gi * iw22);
    if (tid == 0) sm->diag[c] = fmaf(-vcv * vcv, iw22, Tcc + dotd);  // t22n
  }
  __syncthreads();

  // ---------------- Phase F: set diagonal, write out ----------------
  if (tid < P) sm->sT[tid][tid] = sm->diag[tid];
  __syncthreads();
  float* Ob = Out + (size_t)b * (P * P);
  for (int idx = tid; idx < P * P; idx += NT)
    Ob[idx] = sm->sT[idx >> 7][idx & 127];
}

extern "C" void kernel_launch(void* const* d_in, const int* in_sizes, int n_in,
                              void* d_out, int out_size)
{
  const float* Theta = (const float*)d_in[0];
  const float* Lw    = (const float*)d_in[1];
  if (n_in >= 2 && in_sizes[0] < in_sizes[1]) {
    const float* t = Theta; Theta = Lw; Lw = t;
  }
  float* Out = (float*)d_out;

  int Bn = in_sizes[0] / (P * P);   // 128

  cudaFuncSetAttribute(spod_kernel,
                       cudaFuncAttributeMaxDynamicSharedMemorySize,
                       (int)sizeof(Smem));
  spod_kernel<<<Bn, NT, sizeof(Smem)>>>(Theta, Lw, Out);
}

// round 13
// speedup vs baseline: 2.8949x; 2.8949x over previous
#include <cuda_runtime.h>

#define P   128
#define NT  256
#define PT  132   // pitch for sT / sD (skewed)
#define PL  130   // pitch for Lsh

typedef unsigned long long u64;

struct __align__(16) Smem {
  float sT[P][PT];     // Theta (orig), later Theta+Delta (symmetric)
  float sD[P][PT];     // Tc buffer, later Delta (symmetric, zero diag)
  float Lsh[P][PL];    // L_w (127x127, row 127 zeroed)
  float rowk[2][PT];   // sweep: double-buffered modified pivot row
  float tvec[2][PT];   // scan: t-hat (double-buffered, gapped)
  float dvec[2][PT];   // scan: d-hat (double-buffered, gapped)
  float gsh[2][PT];    // scan: W row c (double-buffered, gapped)
  float uvec[2][PT];   // scan: u = W t-hat (double-buffered, uvec[c]=u[c]-1)
  float redT[2][8];
  float redD[2][8];
  float ucvc[2][2];
  float diag[P];
};

// gapped index: halves offset by +4 floats -> warp halves hit different banks
__device__ __forceinline__ int VIDX(int x) { return x + ((x >> 6) << 2); }

__device__ __forceinline__ u64 pk2s(float x) {
  u64 r; asm("mov.b64 %0,{%1,%1};" : "=l"(r) : "f"(x)); return r;
}
__device__ __forceinline__ u64 pk2(float x, float y) {
  u64 r; asm("mov.b64 %0,{%1,%2};" : "=l"(r) : "f"(x), "f"(y)); return r;
}
__device__ __forceinline__ float2 up2(u64 a) {
  float2 f; asm("mov.b64 {%0,%1},%2;" : "=f"(f.x), "=f"(f.y) : "l"(a)); return f;
}
__device__ __forceinline__ u64 f2ma(u64 a, u64 b, u64 c) {
  u64 d; asm("fma.rn.f32x2 %0,%1,%2,%3;" : "=l"(d) : "l"(a), "l"(b), "l"(c));
  return d;
}
__device__ __forceinline__ u64 f2add(u64 a, u64 b) {
  u64 d; asm("add.rn.f32x2 %0,%1,%2;" : "=l"(d) : "l"(a), "l"(b));
  return d;
}
__device__ __forceinline__ float frcp(float x) {
  float r; asm("rcp.approx.f32 %0,%1;" : "=f"(r) : "f"(x)); return r;
}

__global__ void __launch_bounds__(NT, 1)
spod_kernel(const float* __restrict__ Theta,
            const float* __restrict__ Lw,
            float* __restrict__ Out)
{
  extern __shared__ __align__(16) float smraw[];
  Smem* sm = reinterpret_cast<Smem*>(smraw);

  const int tid = threadIdx.x;
  const int b   = blockIdx.x;
  const int i   = tid >> 1;      // row owned by this thread
  const int jh  = tid & 1;       // which 64-column half
  const int j0  = jh << 6;       // 0 or 64
  const int vb  = jh ? 68 : 0;   // VIDX(j0)

  const float* Tin = Theta + (size_t)b * (P * P);

  // ---------------- Phase A: load Theta, L_w ----------------
  for (int idx = tid; idx < P * P; idx += NT)
    sm->sT[idx >> 7][idx & 127] = Tin[idx];
  for (int idx = tid; idx < 127 * 127; idx += NT) {
    int r = idx / 127;
    sm->Lsh[r][idx - r * 127] = Lw[idx];
  }
  if (tid < PL) sm->Lsh[127][tid] = 0.0f;
  if (tid < PT) { sm->uvec[1][tid] = 0.0f; sm->gsh[1][tid] = 0.0f; }
  __syncthreads();

  // ---------------- Phase B0: Tc[m][c] = Theta[m + (m>=c)][c] ----------------
  for (int idx = tid; idx < 127 * P; idx += NT) {
    int m = idx >> 7, c = idx & 127;
    sm->sD[m][c] = sm->sT[m + (m >= c)][c];
  }
  __syncthreads();

  // ---------------- Phase B1: Y = Lsh @ Tc (packed f32x2) ----------------
  const int tj = tid >> 4, ti = tid & 15;
  const int jr = tj * 8, ic = ti * 8;
  u64 acc2[8][4];
  #pragma unroll
  for (int r = 0; r < 8; ++r)
    #pragma unroll
    for (int s = 0; s < 4; ++s) acc2[r][s] = 0ULL;

  #pragma unroll 1
  for (int m = 0; m < 127; ++m) {
    ulonglong2 ta = *(const ulonglong2*)&sm->sD[m][ic];
    ulonglong2 tb = *(const ulonglong2*)&sm->sD[m][ic + 4];
    #pragma unroll
    for (int r = 0; r < 8; ++r) {
      u64 lr = pk2s(sm->Lsh[jr + r][m]);
      acc2[r][0] = f2ma(lr, ta.x, acc2[r][0]);
      acc2[r][1] = f2ma(lr, ta.y, acc2[r][1]);
      acc2[r][2] = f2ma(lr, tb.x, acc2[r][2]);
      acc2[r][3] = f2ma(lr, tb.y, acc2[r][3]);
    }
  }
  __syncthreads();

  // ---------------- Phase B2: Delta (symmetric) into sD ----------------
  #pragma unroll
  for (int r = 0; r < 8; ++r) {
    int j = jr + r;
    #pragma unroll
    for (int s = 0; s < 4; ++s) {
      float2 f = up2(acc2[r][s]);
      int i0 = ic + 2 * s, i1 = i0 + 1;
      if (j < i0) { float d0 = f.x - sm->sT[j][i0]; sm->sD[i0][j] = d0; sm->sD[j][i0] = d0; }
      if (j < i1) { float d1 = f.y - sm->sT[j][i1]; sm->sD[i1][j] = d1; sm->sD[j][i1] = d1; }
    }
  }
  if (tid < P) sm->sD[tid][tid] = 0.0f;
  __syncthreads();

  // ---------------- Phase C: W = inv(Theta) via packed register sweep ----------------
  u64 W2[32];
  #pragma unroll
  for (int t = 0; t < 16; ++t) {
    ulonglong2 v = *(const ulonglong2*)&sm->sT[i][j0 + 4 * t];
    W2[2 * t] = v.x; W2[2 * t + 1] = v.y;
  }

  #pragma unroll 1
  for (int k = 0; k < P; ++k) {
    const int buf = k & 1;
    if (i == k) {
      #pragma unroll
      for (int t = 0; t < 16; ++t) {
        ulonglong2 o; o.x = W2[2 * t]; o.y = W2[2 * t + 1];
        *(ulonglong2*)&sm->rowk[buf][vb + 4 * t] = o;
      }
      if ((k >> 6) == jh) {           // my half holds column k: rkm[k] = d - 1
        float raw = sm->rowk[buf][VIDX(k)];
        sm->rowk[buf][VIDX(k)] = raw - 1.0f;
      }
    }
    __syncthreads();

    float dm1  = sm->rowk[buf][VIDX(k)];
    float invd = frcp(dm1 + 1.0f);
    float ri   = sm->rowk[buf][VIDX(i)];
    float s    = (i == k) ? (1.0f - invd) : (ri * invd);
    u64 ns = pk2s(-s);
    #pragma unroll
    for (int t = 0; t < 16; ++t) {
      ulonglong2 rv = *(const ulonglong2*)&sm->rowk[buf][vb + 4 * t];
      W2[2 * t]     = f2ma(ns, rv.x, W2[2 * t]);
      W2[2 * t + 1] = f2ma(ns, rv.y, W2[2 * t + 1]);
    }
  }

  // negate (sweep gives -A^{-1}), then fix the constant +2 pivot-diag error
  #pragma unroll
  for (int t = 0; t < 32; ++t) W2[t] ^= 0x8000000080000000ULL;
  if ((i >> 6) == jh) {
    int p = i - j0;
    #pragma unroll
    for (int t = 0; t < 32; ++t)
      if (t == (p >> 1)) {
        float2 f = up2(W2[t]);
        if (p & 1) f.y += 2.0f; else f.x += 2.0f;
        W2[t] = pk2(f.x, f.y);
      }
  }

  // ---------------- Phase D: Theta += Delta ----------------
  #pragma unroll
  for (int t = 0; t < 16; ++t) {
    float4 a4 = *(const float4*)&sm->sT[i][j0 + 4 * t];
    float4 d4 = *(const float4*)&sm->sD[i][j0 + 4 * t];
    a4.x += d4.x; a4.y += d4.y; a4.z += d4.z; a4.w += d4.w;
    *(float4*)&sm->sT[i][j0 + 4 * t] = a4;
  }
  __syncthreads();

  // ---------------- Phase E prologue: vectors for c=0 ----------------
  {
    int r5 = tid & 127;
    if (tid < 128) sm->tvec[0][VIDX(r5)] = (r5 == 0) ? 0.0f : sm->sT[0][r5];
    else           sm->dvec[0][VIDX(r5)] = (r5 == 0) ? 0.0f : sm->sD[0][r5];
  }
  __syncthreads();

  // ---------------- Phase E: sequential column scan (1 barrier / step) ----------------
  float e1s = 0.0f, e2s = 0.0f;   // update coefficients from previous step
  #pragma unroll 1
  for (int c = 0; c < P; ++c) {
    const int cb = c & 1;          // current write buffer / tvec read buffer
    const int pb = cb ^ 1;         // previous buffer (gsh/uvec read)
    const int vc = VIDX(c);
    u64 e1p = pk2s(e1s), e2p = pk2s(e2s);

    // -- fused: W += e1*g + e2*u (step c-1), then ua += W t-hat, va += W d-hat --
    u64 ua[4] = {0, 0, 0, 0}, va[4] = {0, 0, 0, 0};
    #pragma unroll
    for (int t = 0; t < 16; ++t) {
      ulonglong2 gv = *(const ulonglong2*)&sm->gsh[pb][vb + 4 * t];
      ulonglong2 uv = *(const ulonglong2*)&sm->uvec[pb][vb + 4 * t];
      u64 w0 = f2ma(e2p, uv.x, f2ma(e1p, gv.x, W2[2 * t]));
      u64 w1 = f2ma(e2p, uv.y, f2ma(e1p, gv.y, W2[2 * t + 1]));
      W2[2 * t] = w0; W2[2 * t + 1] = w1;
      ulonglong2 tv = *(const ulonglong2*)&sm->tvec[cb][vb + 4 * t];
      ulonglong2 dv = *(const ulonglong2*)&sm->dvec[cb][vb + 4 * t];
      ua[(2 * t) & 3]     = f2ma(w0, tv.x, ua[(2 * t) & 3]);
      ua[(2 * t + 1) & 3] = f2ma(w1, tv.y, ua[(2 * t + 1) & 3]);
      va[(2 * t) & 3]     = f2ma(w0, dv.x, va[(2 * t) & 3]);
      va[(2 * t + 1) & 3] = f2ma(w1, dv.y, va[(2 * t + 1) & 3]);
    }
    // packed tail sums: 3 f32x2 adds + 1 scalar add per vector
    float2 au = up2(f2add(f2add(ua[0], ua[1]), f2add(ua[2], ua[3])));
    float up  = au.x + au.y;
    float2 av = up2(f2add(f2add(va[0], va[1]), f2add(va[2], va[3])));
    float vp  = av.x + av.y;

    float ti_ = sm->tvec[cb][VIDX(i)];
    float di_ = sm->dvec[cb][VIDX(i)];
    float s1p = ti_ * up;
    float scp = di_ * vp;

    // combine halves (partner = tid^1, same warp)
    float uf = up + __shfl_xor_sync(0xffffffffu, up, 1);
    float vf = vp + __shfl_xor_sync(0xffffffffu, vp, 1);
    if (jh == 0) {
      if (i == c) {
        sm->ucvc[cb][0] = uf; sm->ucvc[cb][1] = vf;
        sm->uvec[cb][vc] = uf - 1.0f;     // bakes q[c] = -1 into generic update
      } else {
        sm->uvec[cb][VIDX(i)] = uf;
      }
    }
    if (i == c) {   // W2 is W_c now; publish row c for scalars + next update
      #pragma unroll
      for (int t = 0; t < 16; ++t) {
        ulonglong2 o; o.x = W2[2 * t]; o.y = W2[2 * t + 1];
        *(ulonglong2*)&sm->gsh[cb][vb + 4 * t] = o;
      }
    }
    // prefetch next t-hat / d-hat into the other buffer (sT/sD static)
    int cn = c + 1;
    if (cn < P) {
      int r5 = tid & 127;
      if (tid < 128) sm->tvec[pb][VIDX(r5)] = (r5 == cn) ? 0.0f : sm->sT[cn][r5];
      else           sm->dvec[pb][VIDX(r5)] = (r5 == cn) ? 0.0f : sm->sD[cn][r5];
    }

    #pragma unroll
    for (int o = 16; o > 0; o >>= 1) {
      s1p += __shfl_xor_sync(0xffffffffu, s1p, o);
      scp += __shfl_xor_sync(0xffffffffu, scp, o);
    }
    if ((tid & 31) == 0) { sm->redT[cb][tid >> 5] = s1p; sm->redD[cb][tid >> 5] = scp; }
    __syncthreads();

    // -- scalars for step c (parallel-rcp form); applied at start of step c+1 --
    float4 rt0 = *(const float4*)&sm->redT[cb][0];
    float4 rt1 = *(const float4*)&sm->redT[cb][4];
    float4 rd0 = *(const float4*)&sm->redD[cb][0];
    float4 rd1 = *(const float4*)&sm->redD[cb][4];
    float dott = ((rt0.x + rt0.y) + (rt0.z + rt0.w)) + ((rt1.x + rt1.y) + (rt1.z + rt1.w));
    float dotd = ((rd0.x + rd0.y) + (rd0.z + rd0.w)) + ((rd1.x + rd1.y) + (rd1.z + rd1.w));

    float uc   = sm->ucvc[cb][0];
    float vcv  = sm->ucvc[cb][1];
    float w22  = sm->gsh[cb][vc];
    float Tcc  = sm->sT[c][c];
    float iw22 = frcp(w22);
    // w22n = 1/(t22n - s1) = w22 / D,  D = (Tcc + dotd - dott)*w22 + uc^2 - vcv^2
    float D    = fmaf(Tcc + dotd - dott, w22, uc * uc - vcv * vcv);
    float w22n = w22 * frcp(D);                 // two independent rcps
    float alpha = uc * iw22;

    float gi = sm->gsh[cb][VIDX(i)];
    float ui = sm->uvec[cb][VIDX(i)];
    float qi = fmaf(-alpha, gi, ui);
    float cq = w22n * qi;
    e2s = cq;
    e1s = fmaf(-cq, alpha, -gi * iw22);
    if (tid == 0) sm->diag[c] = fmaf(-vcv * vcv, iw22, Tcc + dotd);  // t22n
  }
  __syncthreads();

  // ---------------- Phase F: set diagonal, write out ----------------
  if (tid < P) sm->sT[tid][tid] = sm->diag[tid];
  __syncthreads();
  float* Ob = Out + (size_t)b * (P * P);
  for (int idx = tid; idx < P * P; idx += NT)
    Ob[idx] = sm->sT[idx >> 7][idx & 127];
}

extern "C" void kernel_launch(void* const* d_in, const int* in_sizes, int n_in,
                              void* d_out, int out_size)
{
  const float* Theta = (const float*)d_in[0];
  const float* Lw    = (const float*)d_in[1];
  if (n_in >= 2 && in_sizes[0] < in_sizes[1]) {
    const float* t = Theta; Theta = Lw; Lw = t;
  }
  float* Out = (float*)d_out;

  int Bn = in_sizes[0] / (P * P);   // 128

  cudaFuncSetAttribute(spod_kernel,
                       cudaFuncAttributeMaxDynamicSharedMemorySize,
                       (int)sizeof(Smem));
  spod_kernel<<<Bn, NT, sizeof(Smem)>>>(Theta, Lw, Out);
}

// round 14
// speedup vs baseline: 3.0099x; 1.0397x over previous
#include <cuda_runtime.h>

#define P   128
#define NT  256
#define PT  132   // pitch for sT / sD (skewed)
#define PL  130   // pitch for Lsh

typedef unsigned long long u64;

struct __align__(16) Smem {
  float sT[P][PT];     // Theta (orig), later Theta+Delta (symmetric)
  float sD[P][PT];     // Tc buffer, later Delta (symmetric, zero diag)
  float Lsh[P][PL];    // L_w (127x127, row 127 zeroed)
  float rowA[2][PT];   // sweep: pivot row k   (with [k]   -= 1), dbl-buffered
  float rowB[2][PT];   // sweep: pivot row k+1 (with [k+1] -= 1), dbl-buffered
  float tvec[2][PT];   // scan: t-hat (double-buffered, gapped)
  float dvec[2][PT];   // scan: d-hat (double-buffered, gapped)
  float gsh[2][PT];    // scan: W row c (double-buffered, gapped)
  float uvec[2][PT];   // scan: u = W t-hat (double-buffered, uvec[c]=u[c]-1)
  float redT[2][8];
  float redD[2][8];
  float ucvc[2][2];
  float diag[P];
};

// gapped index: halves offset by +4 floats -> warp halves hit different banks
__device__ __forceinline__ int VIDX(int x) { return x + ((x >> 6) << 2); }

__device__ __forceinline__ u64 pk2s(float x) {
  u64 r; asm("mov.b64 %0,{%1,%1};" : "=l"(r) : "f"(x)); return r;
}
__device__ __forceinline__ u64 pk2(float x, float y) {
  u64 r; asm("mov.b64 %0,{%1,%2};" : "=l"(r) : "f"(x), "f"(y)); return r;
}
__device__ __forceinline__ float2 up2(u64 a) {
  float2 f; asm("mov.b64 {%0,%1},%2;" : "=f"(f.x), "=f"(f.y) : "l"(a)); return f;
}
__device__ __forceinline__ u64 f2ma(u64 a, u64 b, u64 c) {
  u64 d; asm("fma.rn.f32x2 %0,%1,%2,%3;" : "=l"(d) : "l"(a), "l"(b), "l"(c));
  return d;
}
__device__ __forceinline__ u64 f2add(u64 a, u64 b) {
  u64 d; asm("add.rn.f32x2 %0,%1,%2;" : "=l"(d) : "l"(a), "l"(b));
  return d;
}
__device__ __forceinline__ float frcp(float x) {
  float r; asm("rcp.approx.f32 %0,%1;" : "=f"(r) : "f"(x)); return r;
}

__global__ void __launch_bounds__(NT, 1)
spod_kernel(const float* __restrict__ Theta,
            const float* __restrict__ Lw,
            float* __restrict__ Out)
{
  extern __shared__ __align__(16) float smraw[];
  Smem* sm = reinterpret_cast<Smem*>(smraw);

  const int tid = threadIdx.x;
  const int b   = blockIdx.x;
  const int i   = tid >> 1;      // row owned by this thread
  const int jh  = tid & 1;       // which 64-column half
  const int j0  = jh << 6;       // 0 or 64
  const int vb  = jh ? 68 : 0;   // VIDX(j0)

  const float* Tin = Theta + (size_t)b * (P * P);

  // ---------------- Phase A: load Theta, L_w (coalesced) ----------------
  for (int idx = tid; idx < P * P; idx += NT)
    sm->sT[idx >> 7][idx & 127] = Tin[idx];
  for (int idx = tid; idx < 127 * 127; idx += NT) {
    int r = idx / 127;
    sm->Lsh[r][idx - r * 127] = Lw[idx];
  }
  if (tid < PL) sm->Lsh[127][tid] = 0.0f;
  if (tid < PT) { sm->uvec[1][tid] = 0.0f; sm->gsh[1][tid] = 0.0f; }
  __syncthreads();

  // ---------------- Phase B0: Tc[m][c] = Theta[m + (m>=c)][c] ----------------
  for (int idx = tid; idx < 127 * P; idx += NT) {
    int m = idx >> 7, c = idx & 127;
    sm->sD[m][c] = sm->sT[m + (m >= c)][c];
  }
  __syncthreads();

  // ---------------- Phase B1: Y = Lsh @ Tc (packed f32x2) ----------------
  const int tj = tid >> 4, ti = tid & 15;
  const int jr = tj * 8, ic = ti * 8;
  u64 acc2[8][4];
  #pragma unroll
  for (int r = 0; r < 8; ++r)
    #pragma unroll
    for (int s = 0; s < 4; ++s) acc2[r][s] = 0ULL;

  #pragma unroll 1
  for (int m = 0; m < 127; ++m) {
    ulonglong2 ta = *(const ulonglong2*)&sm->sD[m][ic];
    ulonglong2 tb = *(const ulonglong2*)&sm->sD[m][ic + 4];
    #pragma unroll
    for (int r = 0; r < 8; ++r) {
      u64 lr = pk2s(sm->Lsh[jr + r][m]);
      acc2[r][0] = f2ma(lr, ta.x, acc2[r][0]);
      acc2[r][1] = f2ma(lr, ta.y, acc2[r][1]);
      acc2[r][2] = f2ma(lr, tb.x, acc2[r][2]);
      acc2[r][3] = f2ma(lr, tb.y, acc2[r][3]);
    }
  }
  __syncthreads();

  // ---------------- Phase B2: Delta (symmetric) into sD ----------------
  #pragma unroll
  for (int r = 0; r < 8; ++r) {
    int j = jr + r;
    #pragma unroll
    for (int s = 0; s < 4; ++s) {
      float2 f = up2(acc2[r][s]);
      int i0 = ic + 2 * s, i1 = i0 + 1;
      if (j < i0) { float d0 = f.x - sm->sT[j][i0]; sm->sD[i0][j] = d0; sm->sD[j][i0] = d0; }
      if (j < i1) { float d1 = f.y - sm->sT[j][i1]; sm->sD[i1][j] = d1; sm->sD[j][i1] = d1; }
    }
  }
  if (tid < P) sm->sD[tid][tid] = 0.0f;
  __syncthreads();

  // ---------------- Phase C: W = inv(Theta), 2-pivot blocked sweep ----------------
  u64 W2[32];
  #pragma unroll
  for (int t = 0; t < 16; ++t) {
    ulonglong2 v = *(const ulonglong2*)&sm->sT[i][j0 + 4 * t];
    W2[2 * t] = v.x; W2[2 * t + 1] = v.y;
  }

  #pragma unroll 1
  for (int k = 0; k < P; k += 2) {
    const int buf = (k >> 1) & 1;
    if (i == k || i == k + 1) {
      float* dst = (i == k) ? sm->rowA[buf] : sm->rowB[buf];
      #pragma unroll
      for (int t = 0; t < 16; ++t) {
        ulonglong2 o; o.x = W2[2 * t]; o.y = W2[2 * t + 1];
        *(ulonglong2*)&dst[vb + 4 * t] = o;
      }
      if ((i >> 6) == jh)            // my half holds column i: [i] -= 1 fixup
        dst[VIDX(i)] -= 1.0f;
    }
    __syncthreads();

    float a_k  = sm->rowA[buf][VIDX(k)];      // d00 - 1
    float a_k1 = sm->rowA[buf][VIDX(k + 1)];  // d01
    float b_k1 = sm->rowB[buf][VIDX(k + 1)];  // d11 - 1
    float d00 = a_k + 1.0f, d01 = a_k1, d11 = b_k1 + 1.0f;
    float rdet = frcp(fmaf(d00, d11, -d01 * d01));
    float i00 = d11 * rdet, i01 = -d01 * rdet, i11 = d00 * rdet;
    float c1 = sm->rowA[buf][VIDX(i)];
    float c2 = sm->rowB[buf][VIDX(i)];
    float g1 = fmaf(c1, i00, c2 * i01);
    float g2 = fmaf(c1, i01, c2 * i11);
    u64 ng1 = pk2s(-g1), ng2 = pk2s(-g2);
    #pragma unroll
    for (int t = 0; t < 16; ++t) {
      ulonglong2 rA = *(const ulonglong2*)&sm->rowA[buf][vb + 4 * t];
      ulonglong2 rB = *(const ulonglong2*)&sm->rowB[buf][vb + 4 * t];
      W2[2 * t]     = f2ma(ng2, rB.x, f2ma(ng1, rA.x, W2[2 * t]));
      W2[2 * t + 1] = f2ma(ng2, rB.y, f2ma(ng1, rA.y, W2[2 * t + 1]));
    }
  }

  // negate (sweep gives -A^{-1}), then fix the constant +2 pivot-diag error
  #pragma unroll
  for (int t = 0; t < 32; ++t) W2[t] ^= 0x8000000080000000ULL;
  if ((i >> 6) == jh) {
    int p = i - j0;
    #pragma unroll
    for (int t = 0; t < 32; ++t)
      if (t == (p >> 1)) {
        float2 f = up2(W2[t]);
        if (p & 1) f.y += 2.0f; else f.x += 2.0f;
        W2[t] = pk2(f.x, f.y);
      }
  }

  // ---------------- Phase D: Theta += Delta ----------------
  #pragma unroll
  for (int t = 0; t < 16; ++t) {
    float4 a4 = *(const float4*)&sm->sT[i][j0 + 4 * t];
    float4 d4 = *(const float4*)&sm->sD[i][j0 + 4 * t];
    a4.x += d4.x; a4.y += d4.y; a4.z += d4.z; a4.w += d4.w;
    *(float4*)&sm->sT[i][j0 + 4 * t] = a4;
  }
  __syncthreads();

  // ---------------- Phase E prologue: vectors for c=0 ----------------
  {
    int r5 = tid & 127;
    if (tid < 128) sm->tvec[0][VIDX(r5)] = (r5 == 0) ? 0.0f : sm->sT[0][r5];
    else           sm->dvec[0][VIDX(r5)] = (r5 == 0) ? 0.0f : sm->sD[0][r5];
  }
  __syncthreads();

  // ---------------- Phase E: sequential column scan (1 barrier / step) ----------------
  float e1s = 0.0f, e2s = 0.0f;   // update coefficients from previous step
  #pragma unroll 1
  for (int c = 0; c < P; ++c) {
    const int cb = c & 1;          // current write buffer / tvec read buffer
    const int pb = cb ^ 1;         // previous buffer (gsh/uvec read)
    const int vc = VIDX(c);
    u64 e1p = pk2s(e1s), e2p = pk2s(e2s);

    // -- fused: W += e1*g + e2*u (step c-1), then ua += W t-hat, va += W d-hat --
    u64 ua[4] = {0, 0, 0, 0}, va[4] = {0, 0, 0, 0};
    #pragma unroll
    for (int t = 0; t < 16; ++t) {
      ulonglong2 gv = *(const ulonglong2*)&sm->gsh[pb][vb + 4 * t];
      ulonglong2 uv = *(const ulonglong2*)&sm->uvec[pb][vb + 4 * t];
      u64 w0 = f2ma(e2p, uv.x, f2ma(e1p, gv.x, W2[2 * t]));
      u64 w1 = f2ma(e2p, uv.y, f2ma(e1p, gv.y, W2[2 * t + 1]));
      W2[2 * t] = w0; W2[2 * t + 1] = w1;
      ulonglong2 tv = *(const ulonglong2*)&sm->tvec[cb][vb + 4 * t];
      ulonglong2 dv = *(const ulonglong2*)&sm->dvec[cb][vb + 4 * t];
      ua[(2 * t) & 3]     = f2ma(w0, tv.x, ua[(2 * t) & 3]);
      ua[(2 * t + 1) & 3] = f2ma(w1, tv.y, ua[(2 * t + 1) & 3]);
      va[(2 * t) & 3]     = f2ma(w0, dv.x, va[(2 * t) & 3]);
      va[(2 * t + 1) & 3] = f2ma(w1, dv.y, va[(2 * t + 1) & 3]);
    }
    // packed tail sums: 3 f32x2 adds + 1 scalar add per vector
    float2 au = up2(f2add(f2add(ua[0], ua[1]), f2add(ua[2], ua[3])));
    float up  = au.x + au.y;
    float2 av = up2(f2add(f2add(va[0], va[1]), f2add(va[2], va[3])));
    float vp  = av.x + av.y;

    float ti_ = sm->tvec[cb][VIDX(i)];
    float di_ = sm->dvec[cb][VIDX(i)];
    float s1p = ti_ * up;
    float scp = di_ * vp;

    // combine halves (partner = tid^1, same warp)
    float uf = up + __shfl_xor_sync(0xffffffffu, up, 1);
    float vf = vp + __shfl_xor_sync(0xffffffffu, vp, 1);
    if (jh == 0) {
      if (i == c) {
        sm->ucvc[cb][0] = uf; sm->ucvc[cb][1] = vf;
        sm->uvec[cb][vc] = uf - 1.0f;     // bakes q[c] = -1 into generic update
      } else {
        sm->uvec[cb][VIDX(i)] = uf;
      }
    }
    if (i == c) {   // W2 is W_c now; publish row c for scalars + next update
      #pragma unroll
      for (int t = 0; t < 16; ++t) {
        ulonglong2 o; o.x = W2[2 * t]; o.y = W2[2 * t + 1];
        *(ulonglong2*)&sm->gsh[cb][vb + 4 * t] = o;
      }
    }
    // prefetch next t-hat / d-hat into the other buffer (sT/sD static)
    int cn = c + 1;
    if (cn < P) {
      int r5 = tid & 127;
      if (tid < 128) sm->tvec[pb][VIDX(r5)] = (r5 == cn) ? 0.0f : sm->sT[cn][r5];
      else           sm->dvec[pb][VIDX(r5)] = (r5 == cn) ? 0.0f : sm->sD[cn][r5];
    }

    #pragma unroll
    for (int o = 16; o > 0; o >>= 1) {
      s1p += __shfl_xor_sync(0xffffffffu, s1p, o);
      scp += __shfl_xor_sync(0xffffffffu, scp, o);
    }
    if ((tid & 31) == 0) { sm->redT[cb][tid >> 5] = s1p; sm->redD[cb][tid >> 5] = scp; }
    __syncthreads();

    // -- scalars for step c (parallel-rcp form); applied at start of step c+1 --
    float4 rt0 = *(const float4*)&sm->redT[cb][0];
    float4 rt1 = *(const float4*)&sm->redT[cb][4];
    float4 rd0 = *(const float4*)&sm->redD[cb][0];
    float4 rd1 = *(const float4*)&sm->redD[cb][4];
    float dott = ((rt0.x + rt0.y) + (rt0.z + rt0.w)) + ((rt1.x + rt1.y) + (rt1.z + rt1.w));
    float dotd = ((rd0.x + rd0.y) + (rd0.z + rd0.w)) + ((rd1.x + rd1.y) + (rd1.z + rd1.w));

    float uc   = sm->ucvc[cb][0];
    float vcv  = sm->ucvc[cb][1];
    float w22  = sm->gsh[cb][vc];
    float Tcc  = sm->sT[c][c];
    float iw22 = frcp(w22);
    // w22n = 1/(t22n - s1) = w22 / D,  D = (Tcc + dotd - dott)*w22 + uc^2 - vcv^2
    float D    = fmaf(Tcc + dotd - dott, w22, uc * uc - vcv * vcv);
    float w22n = w22 * frcp(D);                 // two independent rcps
    float alpha = uc * iw22;

    float gi = sm->gsh[cb][VIDX(i)];
    float ui = sm->uvec[cb][VIDX(i)];
    float qi = fmaf(-alpha, gi, ui);
    float cq = w22n * qi;
    e2s = cq;
    e1s = fmaf(-cq, alpha, -gi * iw22);
    if (tid == 0) sm->diag[c] = fmaf(-vcv * vcv, iw22, Tcc + dotd);  // t22n
  }
  __syncthreads();

  // ---------------- Phase F: set diagonal, write out ----------------
  if (tid < P) sm->sT[tid][tid] = sm->diag[tid];
  __syncthreads();
  float* Ob = Out + (size_t)b * (P * P);
  for (int idx = tid; idx < P * P; idx += NT)
    Ob[idx] = sm->sT[idx >> 7][idx & 127];
}

extern "C" void kernel_launch(void* const* d_in, const int* in_sizes, int n_in,
                              void* d_out, int out_size)
{
  const float* Theta = (const float*)d_in[0];
  const float* Lw    = (const float*)d_in[1];
  if (n_in >= 2 && in_sizes[0] < in_sizes[1]) {
    const float* t = Theta; Theta = Lw; Lw = t;
  }
  float* Out = (float*)d_out;

  int Bn = in_sizes[0] / (P * P);   // 128

  cudaFuncSetAttribute(spod_kernel,
                       cudaFuncAttributeMaxDynamicSharedMemorySize,
                       (int)sizeof(Smem));
  spod_kernel<<<Bn, NT, sizeof(Smem)>>>(Theta, Lw, Out);
}